// round 1
// baseline (speedup 1.0000x reference)
#include <cuda_runtime.h>
#include <math.h>

#define BB 4
#define LL 4096
#define CC 1024
#define NHH 16
#define CSS 16
#define HFF 64
#define HF4 256
#define NCC 256
#define MROWS (BB*LL)   // 16384

// ---------------- device scratch (module-static; no runtime allocation) -----
__device__ float g_XA[BB*NHH*NCC*CSS*HFF];   // 16,777,216 floats (64MB)
__device__ float g_XB[BB*NHH*NCC*CSS*HFF];
__device__ float g_XC[BB*NHH*NCC*CSS*HFF];
__device__ float g_coef[BB*NHH*NCC*CSS];     // 262,144
__device__ float g_Z2b[(size_t)MROWS*CC];    // 64MB

// ---------------- generic fp32 SGEMM: (16384,1024) x (1024,1024) ------------
// SPLIT=1: store into split layout (b,h,n,s,f). SPLIT=0: plain row-major out.
template<int SPLIT>
__global__ void __launch_bounds__(256) gemm_kernel(const float* __restrict__ A,
                                                   const float* __restrict__ Wm,
                                                   float* __restrict__ out)
{
    __shared__ float As[8][128];
    __shared__ float Bs[8][128];
    const int tid = threadIdx.x;
    const int bm = blockIdx.y, bn = blockIdx.x;
    const int ty = tid >> 4, tx = tid & 15;

    const int arow = tid >> 1;          // 0..127
    const int ak   = (tid & 1) * 4;     // 0 or 4
    const int brow = tid >> 5;          // 0..7
    const int bcol = (tid & 31) * 4;    // 0..124

    const float* Ap = A  + (size_t)(bm*128 + arow)*CC + ak;
    const float* Bp = Wm + (size_t)brow*CC + bn*128 + bcol;

    float acc[8][8];
#pragma unroll
    for (int i=0;i<8;i++)
#pragma unroll
        for (int j=0;j<8;j++) acc[i][j] = 0.f;

    for (int k0 = 0; k0 < CC; k0 += 8) {
        float4 a4 = *(const float4*)(Ap + k0);
        float4 b4 = *(const float4*)(Bp + (size_t)k0*CC);
        __syncthreads();
        As[ak+0][arow] = a4.x;
        As[ak+1][arow] = a4.y;
        As[ak+2][arow] = a4.z;
        As[ak+3][arow] = a4.w;
        *(float4*)&Bs[brow][bcol] = b4;
        __syncthreads();
#pragma unroll
        for (int kk=0; kk<8; kk++) {
            float4 a0 = *(const float4*)&As[kk][ty*4];
            float4 a1 = *(const float4*)&As[kk][64 + ty*4];
            float4 b0 = *(const float4*)&Bs[kk][tx*4];
            float4 b1 = *(const float4*)&Bs[kk][64 + tx*4];
            float av[8] = {a0.x,a0.y,a0.z,a0.w,a1.x,a1.y,a1.z,a1.w};
            float bv[8] = {b0.x,b0.y,b0.z,b0.w,b1.x,b1.y,b1.z,b1.w};
#pragma unroll
            for (int i=0;i<8;i++)
#pragma unroll
                for (int j=0;j<8;j++) acc[i][j] += av[i]*bv[j];
        }
    }

    // epilogue: rows {bm*128 + ih*64 + ty*4 + i}, cols {bn*128 + jh*64 + tx*4 + j}
#pragma unroll
    for (int ih=0; ih<2; ih++) {
#pragma unroll
        for (int i=0;i<4;i++) {
            int r = bm*128 + ih*64 + ty*4 + i;
            int ri = ih*4 + i;
#pragma unroll
            for (int jh=0;jh<2;jh++) {
                int c0 = bn*128 + jh*64 + tx*4;
                float4 v = make_float4(acc[ri][jh*4+0], acc[ri][jh*4+1],
                                       acc[ri][jh*4+2], acc[ri][jh*4+3]);
                if (SPLIT) {
                    int b = r >> 12, l = r & 4095;
                    int n = l >> 4,  s = l & 15;
                    int h = c0 >> 6, f = c0 & 63;
                    size_t idx = ((((size_t)(b*NHH + h)*NCC + n)*CSS + s)*HFF + f);
                    *(float4*)(out + idx) = v;
                } else {
                    *(float4*)(out + (size_t)r*CC + c0) = v;
                }
            }
        }
    }
}

// ---------------- ilr / coeff -----------------------------------------------
__global__ void __launch_bounds__(256) ilr_kernel(const float* __restrict__ hs,
                                                  const float* __restrict__ ilw,
                                                  const float* __restrict__ ilb)
{
    const int h    = threadIdx.x;           // 16
    const int rloc = threadIdx.y;           // 16
    const int row  = blockIdx.x*16 + rloc;
    const float* hp = hs + (size_t)row*CC;
    float a0=0.f, a1=0.f, a2=0.f, a3=0.f;
    for (int k=0;k<CC;k+=4) {
        float4 x = *(const float4*)(hp + k);
        a0 += x.x * ilw[(k+0)*NHH + h];
        a1 += x.y * ilw[(k+1)*NHH + h];
        a2 += x.z * ilw[(k+2)*NHH + h];
        a3 += x.w * ilw[(k+3)*NHH + h];
    }
    float acc = (a0+a1) + (a2+a3) + ilb[h];
    float sig = 1.f / (1.f + expf(-acc));
    int b = row >> 12, l = row & 4095, n = l >> 4, s = l & 15;
    float coef = sig * (1.f/(float)(s+1)) * (1.f/(float)HFF);   // LR = 1.0
    g_coef[((size_t)(b*NHH + h)*NCC + n)*CSS + s] = coef;
}

// ---------------- TTT scan: one CTA per (b,h) chain --------------------------
// shared layout (floats), padded strides to avoid bank conflicts
#define O_W1   0            // 64 x 256            (stride 256)
#define O_W2   16384        // 256 x 65            (stride 65)
#define O_XA   33024        // 16 x 68
#define O_XB   34112
#define O_XC   35200
#define O_XBT  36288        // 64 x 20  (transposed XB)
#define O_Z1   37568        // 16 x 260
#define O_Z1T  41728        // 256 x 20 (transposed Z1)
#define O_G1   46848        // 16 x 260
#define O_Z1B  51008        // 16 x 260
#define O_G2   55168        // 16 x 68
#define O_A1   56256        // 16 x 17
#define O_A2   56528        // 16 x 17
#define O_CO   56800        // 16
#define SCAN_SMEM_FLOATS 56816
#define SCAN_SMEM_BYTES  (SCAN_SMEM_FLOATS*4)

__global__ void __launch_bounds__(256, 1) scan_kernel(const float* __restrict__ W1g,
                                                      const float* __restrict__ W2g)
{
    extern __shared__ float sm[];
    float* sW1  = sm + O_W1;
    float* sW2  = sm + O_W2;
    float* sXA  = sm + O_XA;
    float* sXB  = sm + O_XB;
    float* sXC  = sm + O_XC;
    float* sXBt = sm + O_XBT;
    float* sZ1  = sm + O_Z1;
    float* sZ1t = sm + O_Z1T;
    float* sG1  = sm + O_G1;
    float* sZ1b = sm + O_Z1B;
    float* sG2  = sm + O_G2;
    float* sA1  = sm + O_A1;
    float* sA2  = sm + O_A2;
    float* sCo  = sm + O_CO;

    const int t  = threadIdx.x;
    const int bh = blockIdx.x;
    const int b  = bh >> 4, h = bh & 15;

    // load initial W1[h], W2[h]
    const float* w1p = W1g + (size_t)h*HFF*HF4;
    for (int i = t; i < HFF*HF4; i += 256) sW1[i] = w1p[i];
    const float* w2p = W2g + (size_t)h*HF4*HFF;
    for (int i = t; i < HF4*HFF; i += 256) sW2[(i>>6)*65 + (i&63)] = w2p[i];

    const size_t cbase = (size_t)bh * (NCC*CSS*HFF);

    for (int n = 0; n < NCC; n++) {
        // ---- chunk loads ----
        {
            const float4* xa4 = (const float4*)(g_XA + cbase + (size_t)n*1024);
            const float4* xb4 = (const float4*)(g_XB + cbase + (size_t)n*1024);
            const float4* xc4 = (const float4*)(g_XC + cbase + (size_t)n*1024);
            int e = t*4, s = e >> 6, f = e & 63;
            float4 va = xa4[t], vb = xb4[t], vc = xc4[t];
            *(float4*)(sXA + s*68 + f) = va;
            *(float4*)(sXB + s*68 + f) = vb;
            *(float4*)(sXC + s*68 + f) = vc;
            sXBt[(f+0)*20 + s] = vb.x;
            sXBt[(f+1)*20 + s] = vb.y;
            sXBt[(f+2)*20 + s] = vb.z;
            sXBt[(f+3)*20 + s] = vb.w;
            if (t < 16) sCo[t] = g_coef[(size_t)bh*(NCC*CSS) + n*CSS + t];
        }
        __syncthreads();

        // ---- Step 1: Z1 = XB@W1 and P = XC@W1 (P -> sZ1b) ----
        {
            const int j = t;
            float acc1[16], accP[16];
#pragma unroll
            for (int s=0;s<16;s++){acc1[s]=0.f;accP[s]=0.f;}
#pragma unroll
            for (int kb=0; kb<64; kb+=16) {
                float w[16];
#pragma unroll
                for (int kk=0;kk<16;kk++) w[kk] = sW1[(kb+kk)*256 + j];
#pragma unroll
                for (int s=0;s<16;s++) {
                    const float4* xb = (const float4*)(sXB + s*68 + kb);
                    const float4* xc = (const float4*)(sXC + s*68 + kb);
#pragma unroll
                    for (int q=0;q<4;q++) {
                        float4 vb = xb[q], vc = xc[q];
                        acc1[s] += vb.x*w[4*q] + vb.y*w[4*q+1] + vb.z*w[4*q+2] + vb.w*w[4*q+3];
                        accP[s] += vc.x*w[4*q] + vc.y*w[4*q+1] + vc.z*w[4*q+2] + vc.w*w[4*q+3];
                    }
                }
            }
#pragma unroll
            for (int s=0;s<16;s++) {
                sZ1 [s*260 + j] = acc1[s];
                sZ1t[j*20 + s]  = acc1[s];
                sZ1b[s*260 + j] = accP[s];
            }
        }
        __syncthreads();

        // ---- Step 2: Z2 = Z1@W2 ; g2 = Z2 - XA ----
        {
            const int f = t & 63, si = t >> 6;
            float acc[4] = {0.f,0.f,0.f,0.f};
#pragma unroll 4
            for (int kb=0; kb<256; kb+=4) {
                float w0 = sW2[(kb+0)*65 + f];
                float w1 = sW2[(kb+1)*65 + f];
                float w2 = sW2[(kb+2)*65 + f];
                float w3 = sW2[(kb+3)*65 + f];
#pragma unroll
                for (int q=0;q<4;q++) {
                    const float4 z = *(const float4*)(sZ1 + (si*4+q)*260 + kb);
                    acc[q] += z.x*w0 + z.y*w1 + z.z*w2 + z.w*w3;
                }
            }
#pragma unroll
            for (int q=0;q<4;q++) {
                int s = si*4+q;
                sG2[s*68 + f] = acc[q] - sXA[s*68 + f];
            }
        }
        // ---- Step 4 (same phase, independent): A1 = tril(XC @ XB^T) ----
        {
            const int si = t >> 4, sj = t & 15;
            float acc = 0.f;
            if (sj <= si) {
#pragma unroll
                for (int k=0;k<64;k+=4) {
                    float4 xc = *(const float4*)(sXC + si*68 + k);
                    float4 xb = *(const float4*)(sXB + sj*68 + k);
                    acc += xc.x*xb.x + xc.y*xb.y + xc.z*xb.z + xc.w*xb.w;
                }
            }
            sA1[si*17 + sj] = acc;
        }
        __syncthreads();

        // ---- Step 3: g1 = g2 @ W2^T ----
        {
            const int j = t;
            float acc[16];
#pragma unroll
            for (int s=0;s<16;s++) acc[s]=0.f;
#pragma unroll
            for (int fb=0; fb<64; fb+=16) {
                float w[16];
#pragma unroll
                for (int kk=0;kk<16;kk++) w[kk] = sW2[j*65 + fb + kk];
#pragma unroll
                for (int s=0;s<16;s++) {
                    const float4* g4 = (const float4*)(sG2 + s*68 + fb);
#pragma unroll
                    for (int q=0;q<4;q++) {
                        float4 g = g4[q];
                        acc[s] += g.x*w[4*q] + g.y*w[4*q+1] + g.z*w[4*q+2] + g.w*w[4*q+3];
                    }
                }
            }
#pragma unroll
            for (int s=0;s<16;s++) sG1[s*260 + j] = acc[s];
        }
        __syncthreads();

        // ---- Step 5: Z1_bar = P - coeff*(A1@g1) ; Step 6: W1 -= cl*(XB^T@g1) ----
        {
            const int j = t;
            float g1c[16];
#pragma unroll
            for (int u=0;u<16;u++) g1c[u] = sG1[u*260 + j];
#pragma unroll
            for (int s=0;s<16;s++) {
                float a = 0.f;
                for (int u=0;u<=s;u++) a += sA1[s*17+u]*g1c[u];
                sZ1b[s*260 + j] -= sCo[s]*a;
            }
            const float cl = sCo[15];
#pragma unroll 4
            for (int k=0;k<64;k++) {
                float a = 0.f;
#pragma unroll
                for (int q=0;q<4;q++) {
                    float4 xb = *(const float4*)(sXBt + k*20 + 4*q);
                    a += xb.x*g1c[4*q] + xb.y*g1c[4*q+1] + xb.z*g1c[4*q+2] + xb.w*g1c[4*q+3];
                }
                sW1[k*256 + j] -= cl*a;
            }
        }
        __syncthreads();

        // ---- Step 7: A2 = tril(Z1_bar @ Z1^T) ----
        {
            const int si = t >> 4, sj = t & 15;
            float acc = 0.f;
            if (sj <= si) {
#pragma unroll 8
                for (int k=0;k<256;k+=4) {
                    float4 zb = *(const float4*)(sZ1b + si*260 + k);
                    float4 zz = *(const float4*)(sZ1  + sj*260 + k);
                    acc += zb.x*zz.x + zb.y*zz.y + zb.z*zz.z + zb.w*zz.w;
                }
            }
            sA2[si*17 + sj] = acc;
        }
        __syncthreads();

        // ---- Step 8: Z2_bar = Z1_bar@W2 - coeff*(A2@g2) ; store to g_Z2b ----
        {
            const int f = t & 63, si = t >> 6;
            float acc[4] = {0.f,0.f,0.f,0.f};
#pragma unroll 4
            for (int kb=0; kb<256; kb+=4) {
                float w0 = sW2[(kb+0)*65 + f];
                float w1 = sW2[(kb+1)*65 + f];
                float w2 = sW2[(kb+2)*65 + f];
                float w3 = sW2[(kb+3)*65 + f];
#pragma unroll
                for (int q=0;q<4;q++) {
                    const float4 z = *(const float4*)(sZ1b + (si*4+q)*260 + kb);
                    acc[q] += z.x*w0 + z.y*w1 + z.z*w2 + z.w*w3;
                }
            }
            float* orow = g_Z2b + (size_t)(b*LL + n*CSS)*CC + h*HFF + f;
#pragma unroll
            for (int q=0;q<4;q++) {
                int s = si*4+q;
                float c = 0.f;
                for (int u=0;u<=s;u++) c += sA2[s*17+u]*sG2[u*68+f];
                orow[(size_t)s*CC] = acc[q] - sCo[s]*c;
            }
        }
        __syncthreads();

        // ---- Step 9: W2 -= cl*(Z1^T @ g2) ----
        {
            const int f = t & 63, ko = t >> 6;
            float g2c[16];
#pragma unroll
            for (int s=0;s<16;s++) g2c[s] = sG2[s*68 + f];
            const float cl = sCo[15];
#pragma unroll 2
            for (int i=0;i<64;i++) {
                int k = ko*64 + i;
                float a = 0.f;
#pragma unroll
                for (int q=0;q<4;q++) {
                    float4 z = *(const float4*)(sZ1t + k*20 + 4*q);
                    a += z.x*g2c[4*q] + z.y*g2c[4*q+1] + z.z*g2c[4*q+2] + z.w*g2c[4*q+3];
                }
                sW2[k*65 + f] -= cl*a;
            }
        }
        __syncthreads();
    }
}

// ---------------- launch -----------------------------------------------------
extern "C" void kernel_launch(void* const* d_in, const int* in_sizes, int n_in,
                              void* d_out, int out_size)
{
    const float* hs  = (const float*)d_in[0];
    const float* Wq  = (const float*)d_in[1];
    const float* Wk  = (const float*)d_in[2];
    const float* Wv  = (const float*)d_in[3];
    const float* Wo  = (const float*)d_in[4];
    const float* ilw = (const float*)d_in[5];
    const float* ilb = (const float*)d_in[6];
    const float* W1  = (const float*)d_in[7];
    const float* W2  = (const float*)d_in[8];
    float* out = (float*)d_out;

    cudaFuncSetAttribute(scan_kernel, cudaFuncAttributeMaxDynamicSharedMemorySize,
                         SCAN_SMEM_BYTES);

    void *pXA, *pXB, *pXC, *pZ2b;
    cudaGetSymbolAddress(&pXA, g_XA);
    cudaGetSymbolAddress(&pXB, g_XB);
    cudaGetSymbolAddress(&pXC, g_XC);
    cudaGetSymbolAddress(&pZ2b, g_Z2b);

    dim3 gg(CC/128, MROWS/128);   // (8, 128)
    gemm_kernel<1><<<gg, 256>>>(hs, Wq, (float*)pXC);
    gemm_kernel<1><<<gg, 256>>>(hs, Wk, (float*)pXB);
    gemm_kernel<1><<<gg, 256>>>(hs, Wv, (float*)pXA);
    ilr_kernel<<<MROWS/16, dim3(16,16)>>>(hs, ilw, ilb);
    scan_kernel<<<BB*NHH, 256, SCAN_SMEM_BYTES>>>(W1, W2);
    gemm_kernel<0><<<gg, 256>>>((const float*)pZ2b, Wo, out);
}

// round 2
// speedup vs baseline: 1.0160x; 1.0160x over previous
#include <cuda_runtime.h>
#include <math.h>
#include <stdint.h>

#define BB 4
#define LL 4096
#define CC 1024
#define NHH 16
#define CSS 16
#define HFF 64
#define HF4 256
#define NCC 256
#define MROWS (BB*LL)   // 16384

// ---------------- device scratch -----------------
__device__ float g_XA[BB*NHH*NCC*CSS*HFF];
__device__ float g_XB[BB*NHH*NCC*CSS*HFF];
__device__ float g_XC[BB*NHH*NCC*CSS*HFF];
__device__ float g_coef[BB*NHH*NCC*CSS];
__device__ float g_Z2b[(size_t)MROWS*CC];

// ---------------- helpers -----------------
__device__ __forceinline__ float to_tf32(float x){
    uint32_t u; asm("cvt.rna.tf32.f32 %0, %1;" : "=r"(u) : "f"(x));
    return __uint_as_float(u);
}
__device__ __forceinline__ void ldsm4(uint32_t* r, uint32_t addr){
    asm volatile("ldmatrix.sync.aligned.m8n8.x4.shared.b16 {%0,%1,%2,%3}, [%4];"
        : "=r"(r[0]),"=r"(r[1]),"=r"(r[2]),"=r"(r[3]) : "r"(addr));
}
__device__ __forceinline__ void mma_tf32(float* c, const uint32_t* a, uint32_t b0, uint32_t b1){
    asm volatile("mma.sync.aligned.m16n8k8.row.col.f32.tf32.tf32.f32 "
        "{%0,%1,%2,%3},{%4,%5,%6,%7},{%8,%9},{%0,%1,%2,%3};"
        : "+f"(c[0]),"+f"(c[1]),"+f"(c[2]),"+f"(c[3])
        : "r"(a[0]),"r"(a[1]),"r"(a[2]),"r"(a[3]),"r"(b0),"r"(b1));
}
__device__ __forceinline__ float peer_f(uint32_t laddr, uint32_t peer){
    uint32_t ra; asm("mapa.shared::cluster.u32 %0, %1, %2;" : "=r"(ra) : "r"(laddr), "r"(peer));
    float v; asm volatile("ld.shared::cluster.f32 %0, [%1];" : "=f"(v) : "r"(ra));
    return v;
}
#define CLUSTER_SYNC() do{ \
    asm volatile("barrier.cluster.arrive.aligned;" ::: "memory"); \
    asm volatile("barrier.cluster.wait.aligned;"   ::: "memory"); }while(0)

// ---------------- tf32 tensor-core GEMM: (16384,1024)x(1024,1024) ------------
// block 128x128, k-tile 32. 8 warps: wm(4) x wn(2), warp tile 32x64.
// SPLIT=1: scatter into (b,h,n,s,f) layout; SPLIT=0: row-major.
#define GPAD 36
template<int SPLIT>
__global__ void __launch_bounds__(256) gemm_tf32(const float* __restrict__ A,
                                                 const float* __restrict__ Wm,
                                                 float* __restrict__ out)
{
    __shared__ float As[128*GPAD];
    __shared__ float Bs[128*GPAD];
    const int t = threadIdx.x, lane = t & 31, warp = t >> 5;
    const int wm = warp >> 1, wn = warp & 1;
    const int bm = blockIdx.y, bn = blockIdx.x;

    float acc[2][8][4];
#pragma unroll
    for (int i=0;i<2;i++)
#pragma unroll
        for (int j=0;j<8;j++)
#pragma unroll
            for (int q=0;q<4;q++) acc[i][j][q]=0.f;

    uint32_t As_u = (uint32_t)__cvta_generic_to_shared(As);
    uint32_t Bs_u = (uint32_t)__cvta_generic_to_shared(Bs);

    uint32_t a_addr[2], b_addr[4];
#pragma unroll
    for (int mf=0; mf<2; mf++) {
        int row = wm*32 + mf*16 + (lane & 15);
        a_addr[mf] = As_u + (uint32_t)(row*GPAD + (lane>>4)*4) * 4u;
    }
#pragma unroll
    for (int nf2=0; nf2<4; nf2++) {
        int nr = wn*64 + nf2*16 + (lane & 7) + ((lane>>4)&1)*8;
        b_addr[nf2] = Bs_u + (uint32_t)(nr*GPAD + ((lane>>3)&1)*4) * 4u;
    }

    const float* Ab = A  + (size_t)(bm*128)*CC;
    const float* Bb = Wm + bn*128;

    float4 ar[4], br[4];
#pragma unroll
    for (int i=0;i<4;i++){
        int p = t + i*256;
        ar[i] = *(const float4*)(Ab + (size_t)(p>>3)*CC + (p&7)*4);
        br[i] = *(const float4*)(Bb + (size_t)(p>>5)*CC + (p&31)*4);
    }

    for (int it=0; it<32; it++){
        __syncthreads();
#pragma unroll
        for (int i=0;i<4;i++){
            int p = t + i*256;
            float4 v = ar[i];
            float4 w = make_float4(to_tf32(v.x), to_tf32(v.y), to_tf32(v.z), to_tf32(v.w));
            *(float4*)&As[(p>>3)*GPAD + (p&7)*4] = w;
        }
#pragma unroll
        for (int i=0;i<4;i++){
            int p = t + i*256;
            float4 v = br[i];
            int nc = (p&31)*4, kr = p>>5;
            Bs[(nc+0)*GPAD + kr] = to_tf32(v.x);
            Bs[(nc+1)*GPAD + kr] = to_tf32(v.y);
            Bs[(nc+2)*GPAD + kr] = to_tf32(v.z);
            Bs[(nc+3)*GPAD + kr] = to_tf32(v.w);
        }
        __syncthreads();
        if (it < 31){
            const float* Ab2 = Ab + (it+1)*32;
            const float* Bb2 = Bb + (size_t)(it+1)*32*CC;
#pragma unroll
            for (int i=0;i<4;i++){
                int p = t + i*256;
                ar[i] = *(const float4*)(Ab2 + (size_t)(p>>3)*CC + (p&7)*4);
                br[i] = *(const float4*)(Bb2 + (size_t)(p>>5)*CC + (p&31)*4);
            }
        }
#pragma unroll
        for (int s8=0; s8<4; s8++){
            uint32_t a[2][4], bf[4][4];
            ldsm4(a[0], a_addr[0] + s8*32);
            ldsm4(a[1], a_addr[1] + s8*32);
            ldsm4(bf[0], b_addr[0] + s8*32);
            ldsm4(bf[1], b_addr[1] + s8*32);
            ldsm4(bf[2], b_addr[2] + s8*32);
            ldsm4(bf[3], b_addr[3] + s8*32);
#pragma unroll
            for (int mf=0; mf<2; mf++)
#pragma unroll
                for (int nf=0; nf<8; nf++)
                    mma_tf32(acc[mf][nf], a[mf], bf[nf>>1][(nf&1)*2], bf[nf>>1][(nf&1)*2+1]);
        }
    }

    // epilogue
#pragma unroll
    for (int mf=0; mf<2; mf++){
#pragma unroll
        for (int nf=0; nf<8; nf++){
            int r = bm*128 + wm*32 + mf*16 + (lane>>2);
            int c = bn*128 + wn*64 + nf*8 + (lane&3)*2;
#pragma unroll
            for (int half=0; half<2; half++){
                int rr = r + half*8;
                float2 v = make_float2(acc[mf][nf][half*2], acc[mf][nf][half*2+1]);
                if (SPLIT){
                    int b = rr >> 12, l = rr & 4095;
                    int n = l >> 4, s = l & 15;
                    int h = c >> 6, f = c & 63;
                    size_t idx = ((((size_t)(b*NHH + h)*NCC + n)*CSS + s)*HFF + f);
                    *(float2*)(out + idx) = v;
                } else {
                    *(float2*)(out + (size_t)rr*CC + c) = v;
                }
            }
        }
    }
}

// ---------------- ilr / coeff -----------------
__global__ void __launch_bounds__(256) ilr_kernel(const float* __restrict__ hs,
                                                  const float* __restrict__ ilw,
                                                  const float* __restrict__ ilb)
{
    const int h = threadIdx.x, rloc = threadIdx.y;
    const int row = blockIdx.x*16 + rloc;
    const float* hp = hs + (size_t)row*CC;
    float a0=0.f,a1=0.f,a2=0.f,a3=0.f;
    for (int k=0;k<CC;k+=4){
        float4 x = *(const float4*)(hp + k);
        a0 += x.x*ilw[(k+0)*NHH+h];
        a1 += x.y*ilw[(k+1)*NHH+h];
        a2 += x.z*ilw[(k+2)*NHH+h];
        a3 += x.w*ilw[(k+3)*NHH+h];
    }
    float acc = (a0+a1)+(a2+a3) + ilb[h];
    float sig = 1.f/(1.f+expf(-acc));
    int b = row>>12, l = row&4095, n = l>>4, s = l&15;
    g_coef[((size_t)(b*NHH+h)*NCC+n)*CSS+s] = sig*(1.f/(float)(s+1))*(1.f/(float)HFF);
}

// ---------------- TTT scan: cluster of 2 CTAs per (b,h); hidden dim split ----
// local hidden cols: 128 per CTA
#define O_W1   0            // 64 x 128
#define O_W2   8192         // 128 x 65
#define O_XA   16512        // 16 x 68
#define O_XB   17600
#define O_XC   18688
#define O_XBT  19776        // 64 x 20
#define O_Z1   21056        // 16 x 132
#define O_Z1T  23168        // 128 x 20
#define O_G1   25728        // 16 x 132
#define O_Z1B  27840        // 16 x 132
#define O_G2   29952        // 16 x 68
#define O_Z2P  31040        // 16 x 68
#define O_Z2BP 32128        // 16 x 68
#define O_A1   33216        // 16 x 17
#define O_A2P  33488
#define O_A2   33760
#define O_CO   34032        // 16
#define SCAN_SMEM_FLOATS 34048
#define SCAN_SMEM_BYTES  (SCAN_SMEM_FLOATS*4)

__global__ void __launch_bounds__(256,1) __cluster_dims__(2,1,1)
scan_kernel(const float* __restrict__ W1g, const float* __restrict__ W2g)
{
    extern __shared__ float sm[];
    float* sW1  = sm + O_W1;
    float* sW2  = sm + O_W2;
    float* sXA  = sm + O_XA;
    float* sXB  = sm + O_XB;
    float* sXC  = sm + O_XC;
    float* sXBt = sm + O_XBT;
    float* sZ1  = sm + O_Z1;
    float* sZ1t = sm + O_Z1T;
    float* sG1  = sm + O_G1;
    float* sZ1b = sm + O_Z1B;
    float* sG2  = sm + O_G2;
    float* sZ2p = sm + O_Z2P;
    float* sZ2bp= sm + O_Z2BP;
    float* sA1  = sm + O_A1;
    float* sA2p = sm + O_A2P;
    float* sA2  = sm + O_A2;
    float* sCo  = sm + O_CO;

    const int t = threadIdx.x;
    uint32_t rank; asm("mov.u32 %0, %%cluster_ctarank;" : "=r"(rank));
    const uint32_t peer = rank ^ 1u;
    const int bh = blockIdx.x >> 1;
    const int b = bh >> 4, h = bh & 15;
    const uint32_t smb = (uint32_t)__cvta_generic_to_shared(sm);

    // load local W1 columns, W2 rows
    const float* w1p = W1g + (size_t)h*HFF*HF4;
    for (int i=t; i<HFF*128; i+=256){ int k=i>>7, j=i&127; sW1[k*128+j] = w1p[(size_t)k*HF4 + rank*128 + j]; }
    const float* w2p = W2g + (size_t)h*HF4*HFF;
    for (int i=t; i<128*HFF; i+=256){ int k=i>>6, f=i&63; sW2[k*65+f] = w2p[(size_t)(rank*128+k)*HFF + f]; }

    const size_t cbase = (size_t)bh * (NCC*CSS*HFF);
    const int jl = t & 127, sh = t >> 7;   // hidden-col mapping
    const int f6 = t & 63, si4 = t >> 6;   // (s-quad, feature) mapping
    const int si = t >> 4, sj = t & 15;    // attn mapping

    for (int n = 0; n < NCC; n++) {
        // ---- chunk loads ----
        {
            const float4* xa4 = (const float4*)(g_XA + cbase + (size_t)n*1024);
            const float4* xb4 = (const float4*)(g_XB + cbase + (size_t)n*1024);
            const float4* xc4 = (const float4*)(g_XC + cbase + (size_t)n*1024);
            int e = t*4, s = e >> 6, f = e & 63;
            float4 va = xa4[t], vb = xb4[t], vc = xc4[t];
            *(float4*)(sXA + s*68 + f) = va;
            *(float4*)(sXB + s*68 + f) = vb;
            *(float4*)(sXC + s*68 + f) = vc;
            sXBt[(f+0)*20 + s] = vb.x;
            sXBt[(f+1)*20 + s] = vb.y;
            sXBt[(f+2)*20 + s] = vb.z;
            sXBt[(f+3)*20 + s] = vb.w;
            if (t < 16) sCo[t] = g_coef[(size_t)bh*(NCC*CSS) + n*CSS + t];
        }
        __syncthreads();

        // ---- Step 1: Z1 = XB@W1_loc, P = XC@W1_loc (8 s-rows per thread) ----
        {
            float acc1[8], accP[8];
#pragma unroll
            for (int i=0;i<8;i++){acc1[i]=0.f;accP[i]=0.f;}
#pragma unroll
            for (int kb=0; kb<64; kb+=16){
                float w[16];
#pragma unroll
                for (int kk=0;kk<16;kk++) w[kk] = sW1[(kb+kk)*128 + jl];
#pragma unroll
                for (int s2=0;s2<8;s2++){
                    int s = sh*8 + s2;
                    const float4* xb = (const float4*)(sXB + s*68 + kb);
                    const float4* xc = (const float4*)(sXC + s*68 + kb);
#pragma unroll
                    for (int q=0;q<4;q++){
                        float4 vb = xb[q], vc = xc[q];
                        acc1[s2] += vb.x*w[4*q]+vb.y*w[4*q+1]+vb.z*w[4*q+2]+vb.w*w[4*q+3];
                        accP[s2] += vc.x*w[4*q]+vc.y*w[4*q+1]+vc.z*w[4*q+2]+vc.w*w[4*q+3];
                    }
                }
            }
#pragma unroll
            for (int s2=0;s2<8;s2++){
                int s = sh*8 + s2;
                sZ1 [s*132 + jl] = acc1[s2];
                sZ1t[jl*20 + s]  = acc1[s2];
                sZ1b[s*132 + jl] = accP[s2];
            }
        }
        __syncthreads();

        // ---- Step 2: Z2 partial = Z1_loc @ W2_loc ----
        {
            float acc[4] = {0.f,0.f,0.f,0.f};
#pragma unroll 4
            for (int kb=0; kb<128; kb+=4){
                float w0 = sW2[(kb+0)*65 + f6];
                float w1 = sW2[(kb+1)*65 + f6];
                float w2 = sW2[(kb+2)*65 + f6];
                float w3 = sW2[(kb+3)*65 + f6];
#pragma unroll
                for (int q=0;q<4;q++){
                    const float4 z = *(const float4*)(sZ1 + (si4*4+q)*132 + kb);
                    acc[q] += z.x*w0 + z.y*w1 + z.z*w2 + z.w*w3;
                }
            }
#pragma unroll
            for (int q=0;q<4;q++) sZ2p[(si4*4+q)*68 + f6] = acc[q];
        }
        // ---- A1 = tril(XC @ XB^T) (local duplicate) ----
        {
            float acc = 0.f;
            if (sj <= si){
#pragma unroll
                for (int k=0;k<64;k+=4){
                    float4 xc = *(const float4*)(sXC + si*68 + k);
                    float4 xb = *(const float4*)(sXB + sj*68 + k);
                    acc += xc.x*xb.x + xc.y*xb.y + xc.z*xb.z + xc.w*xb.w;
                }
            }
            sA1[si*17 + sj] = acc;
        }
        CLUSTER_SYNC();   // Z2 partials visible both sides

        // ---- g2 = Z2p_own + Z2p_peer - XA ----
        {
            float pv[4];
#pragma unroll
            for (int q=0;q<4;q++)
                pv[q] = peer_f(smb + (O_Z2P + (si4*4+q)*68 + f6)*4u, peer);
#pragma unroll
            for (int q=0;q<4;q++){
                int s = si4*4+q;
                sG2[s*68 + f6] = sZ2p[s*68 + f6] + pv[q] - sXA[s*68 + f6];
            }
        }
        __syncthreads();

        // ---- Step 3: g1_loc = g2 @ W2_loc^T ----
        {
            float acc[8];
#pragma unroll
            for (int i=0;i<8;i++) acc[i]=0.f;
#pragma unroll
            for (int fb=0; fb<64; fb+=16){
                float w[16];
#pragma unroll
                for (int kk=0;kk<16;kk++) w[kk] = sW2[jl*65 + fb + kk];
#pragma unroll
                for (int s2=0;s2<8;s2++){
                    int s = sh*8 + s2;
                    const float4* g4 = (const float4*)(sG2 + s*68 + fb);
#pragma unroll
                    for (int q=0;q<4;q++){
                        float4 g = g4[q];
                        acc[s2] += g.x*w[4*q]+g.y*w[4*q+1]+g.z*w[4*q+2]+g.w*w[4*q+3];
                    }
                }
            }
#pragma unroll
            for (int s2=0;s2<8;s2++) sG1[(sh*8+s2)*132 + jl] = acc[s2];
        }
        __syncthreads();

        // ---- Step 5: Z1b_loc -= co*(A1@g1_loc) ; W1_loc update ----
        {
            float g1c[16];
#pragma unroll
            for (int u=0;u<16;u++) g1c[u] = sG1[u*132 + jl];
#pragma unroll
            for (int s2=0;s2<8;s2++){
                int s = sh*8 + s2;
                float a = 0.f;
                for (int u=0;u<=s;u++) a += sA1[s*17+u]*g1c[u];
                sZ1b[s*132 + jl] -= sCo[s]*a;
            }
            const float cl = sCo[15];
#pragma unroll 4
            for (int i=0;i<32;i++){
                int k = sh*32 + i;
                float a = 0.f;
#pragma unroll
                for (int q=0;q<4;q++){
                    float4 xb = *(const float4*)(sXBt + k*20 + 4*q);
                    a += xb.x*g1c[4*q]+xb.y*g1c[4*q+1]+xb.z*g1c[4*q+2]+xb.w*g1c[4*q+3];
                }
                sW1[k*128 + jl] -= cl*a;
            }
        }
        __syncthreads();

        // ---- Step 7: A2 partial ; Step 8a: Z2b partial ----
        {
            float acc = 0.f;
            if (sj <= si){
#pragma unroll 8
                for (int k=0;k<128;k+=4){
                    float4 zb = *(const float4*)(sZ1b + si*132 + k);
                    float4 zz = *(const float4*)(sZ1  + sj*132 + k);
                    acc += zb.x*zz.x + zb.y*zz.y + zb.z*zz.z + zb.w*zz.w;
                }
            }
            sA2p[si*17 + sj] = acc;
        }
        {
            float acc[4] = {0.f,0.f,0.f,0.f};
#pragma unroll 4
            for (int kb=0; kb<128; kb+=4){
                float w0 = sW2[(kb+0)*65 + f6];
                float w1 = sW2[(kb+1)*65 + f6];
                float w2 = sW2[(kb+2)*65 + f6];
                float w3 = sW2[(kb+3)*65 + f6];
#pragma unroll
                for (int q=0;q<4;q++){
                    const float4 z = *(const float4*)(sZ1b + (si4*4+q)*132 + kb);
                    acc[q] += z.x*w0 + z.y*w1 + z.z*w2 + z.w*w3;
                }
            }
#pragma unroll
            for (int q=0;q<4;q++) sZ2bp[(si4*4+q)*68 + f6] = acc[q];
        }
        CLUSTER_SYNC();   // A2/Z2b partials visible both sides

        // ---- A2 full = own + peer ----
        sA2[si*17 + sj] = sA2p[si*17 + sj] + peer_f(smb + (O_A2P + si*17 + sj)*4u, peer);
        __syncthreads();

        // ---- finalize Z2_bar for this rank's 8 s-rows; write to global ----
        {
            int sl = si4;   // 0..3
#pragma unroll
            for (int j=0;j<2;j++){
                int s = (int)rank*8 + sl*2 + j;
                float pv = peer_f(smb + (O_Z2BP + s*68 + f6)*4u, peer);
                float corr = 0.f;
                for (int u=0;u<=s;u++) corr += sA2[s*17+u]*sG2[u*68+f6];
                float val = sZ2bp[s*68 + f6] + pv - sCo[s]*corr;
                g_Z2b[(size_t)(b*LL + n*CSS + s)*CC + h*HFF + f6] = val;
            }
        }
        // ---- Step 9: W2_loc -= cl*(Z1_loc^T @ g2) ----
        {
            float g2c[16];
#pragma unroll
            for (int s=0;s<16;s++) g2c[s] = sG2[s*68 + f6];
            const float cl = sCo[15];
#pragma unroll 4
            for (int i=0;i<32;i++){
                int k = si4*32 + i;
                float a = 0.f;
#pragma unroll
                for (int q=0;q<4;q++){
                    float4 z = *(const float4*)(sZ1t + k*20 + 4*q);
                    a += z.x*g2c[4*q]+z.y*g2c[4*q+1]+z.z*g2c[4*q+2]+z.w*g2c[4*q+3];
                }
                sW2[k*65 + f6] -= cl*a;
            }
        }
        __syncthreads();
    }
    CLUSTER_SYNC();  // keep smem alive until peer finishes its last reads
}

// ---------------- launch -----------------
extern "C" void kernel_launch(void* const* d_in, const int* in_sizes, int n_in,
                              void* d_out, int out_size)
{
    const float* hs  = (const float*)d_in[0];
    const float* Wq  = (const float*)d_in[1];
    const float* Wk  = (const float*)d_in[2];
    const float* Wv  = (const float*)d_in[3];
    const float* Wo  = (const float*)d_in[4];
    const float* ilw = (const float*)d_in[5];
    const float* ilb = (const float*)d_in[6];
    const float* W1  = (const float*)d_in[7];
    const float* W2  = (const float*)d_in[8];
    float* out = (float*)d_out;

    cudaFuncSetAttribute(scan_kernel, cudaFuncAttributeMaxDynamicSharedMemorySize,
                         SCAN_SMEM_BYTES);

    void *pXA, *pXB, *pXC, *pZ2b;
    cudaGetSymbolAddress(&pXA, g_XA);
    cudaGetSymbolAddress(&pXB, g_XB);
    cudaGetSymbolAddress(&pXC, g_XC);
    cudaGetSymbolAddress(&pZ2b, g_Z2b);

    dim3 gg(CC/128, MROWS/128);   // (8, 128)
    gemm_tf32<1><<<gg, 256>>>(hs, Wq, (float*)pXC);
    gemm_tf32<1><<<gg, 256>>>(hs, Wk, (float*)pXB);
    gemm_tf32<1><<<gg, 256>>>(hs, Wv, (float*)pXA);
    ilr_kernel<<<MROWS/16, dim3(16,16)>>>(hs, ilw, ilb);
    scan_kernel<<<BB*NHH*2, 256, SCAN_SMEM_BYTES>>>(W1, W2);
    gemm_tf32<0><<<gg, 256>>>((const float*)pZ2b, Wo, out);
}

// round 3
// speedup vs baseline: 1.2096x; 1.1905x over previous
#include <cuda_runtime.h>
#include <math.h>
#include <stdint.h>

#define BB 4
#define LL 4096
#define CC 1024
#define NHH 16
#define CSS 16
#define HFF 64
#define HF4 256
#define NCC 256
#define MROWS (BB*LL)   // 16384

// ---------------- device scratch -----------------
__device__ float g_XA[BB*NHH*NCC*CSS*HFF];
__device__ float g_XB[BB*NHH*NCC*CSS*HFF];
__device__ float g_XC[BB*NHH*NCC*CSS*HFF];
__device__ float g_coef[BB*NHH*NCC*CSS];
__device__ float g_Z2b[(size_t)MROWS*CC];

// ---------------- helpers -----------------
__device__ __forceinline__ float to_tf32(float x){
    uint32_t u; asm("cvt.rna.tf32.f32 %0, %1;" : "=r"(u) : "f"(x));
    return __uint_as_float(u);
}
__device__ __forceinline__ void ldsm4(uint32_t* r, uint32_t addr){
    asm volatile("ldmatrix.sync.aligned.m8n8.x4.shared.b16 {%0,%1,%2,%3}, [%4];"
        : "=r"(r[0]),"=r"(r[1]),"=r"(r[2]),"=r"(r[3]) : "r"(addr));
}
__device__ __forceinline__ void mma_tf32(float* c, const uint32_t* a, uint32_t b0, uint32_t b1){
    asm volatile("mma.sync.aligned.m16n8k8.row.col.f32.tf32.tf32.f32 "
        "{%0,%1,%2,%3},{%4,%5,%6,%7},{%8,%9},{%0,%1,%2,%3};"
        : "+f"(c[0]),"+f"(c[1]),"+f"(c[2]),"+f"(c[3])
        : "r"(a[0]),"r"(a[1]),"r"(a[2]),"r"(a[3]),"r"(b0),"r"(b1));
}

// ---------------- tf32 tensor-core GEMM: (16384,1024)x(1024,1024) ------------
// block 128x128, k-tile 32. 8 warps: wm(4) x wn(2), warp tile 32x64.
// A smem: [128 m][36 k] (GPAD=36, ldmatrix conflict-free)
// B smem: [32 k][132 n] (K-major, STS.128 conflict-free, frag LDS 2-way max)
#define GPAD 36
#define BSN  132
template<int SPLIT>
__global__ void __launch_bounds__(256) gemm_tf32(const float* __restrict__ A,
                                                 const float* __restrict__ Wm,
                                                 float* __restrict__ out)
{
    __shared__ float As[128*GPAD];
    __shared__ float Bs[32*BSN];
    const int t = threadIdx.x, lane = t & 31, warp = t >> 5;
    const int wm = warp >> 1, wn = warp & 1;
    const int bm = blockIdx.y, bn = blockIdx.x;

    float acc[2][8][4];
#pragma unroll
    for (int i=0;i<2;i++)
#pragma unroll
        for (int j=0;j<8;j++)
#pragma unroll
            for (int q=0;q<4;q++) acc[i][j][q]=0.f;

    uint32_t As_u = (uint32_t)__cvta_generic_to_shared(As);

    uint32_t a_addr[2];
#pragma unroll
    for (int mf=0; mf<2; mf++) {
        int row = wm*32 + mf*16 + (lane & 15);
        a_addr[mf] = As_u + (uint32_t)(row*GPAD + (lane>>4)*4) * 4u;
    }

    const float* Ab = A  + (size_t)(bm*128)*CC;
    const float* Bb = Wm + bn*128;

    float4 ar[4], br[4];
#pragma unroll
    for (int i=0;i<4;i++){
        int p = t + i*256;
        ar[i] = *(const float4*)(Ab + (size_t)(p>>3)*CC + (p&7)*4);
        br[i] = *(const float4*)(Bb + (size_t)(p>>5)*CC + (p&31)*4);
    }

    for (int it=0; it<32; it++){
        __syncthreads();
#pragma unroll
        for (int i=0;i<4;i++){
            int p = t + i*256;
            float4 v = ar[i];
            float4 w = make_float4(to_tf32(v.x), to_tf32(v.y), to_tf32(v.z), to_tf32(v.w));
            *(float4*)&As[(p>>3)*GPAD + (p&7)*4] = w;
        }
#pragma unroll
        for (int i=0;i<4;i++){
            int p = t + i*256;
            float4 v = br[i];
            float4 w = make_float4(to_tf32(v.x), to_tf32(v.y), to_tf32(v.z), to_tf32(v.w));
            *(float4*)&Bs[(p>>5)*BSN + (p&31)*4] = w;   // K-major, conflict-free
        }
        __syncthreads();
        if (it < 31){
            const float* Ab2 = Ab + (it+1)*32;
            const float* Bb2 = Bb + (size_t)(it+1)*32*CC;
#pragma unroll
            for (int i=0;i<4;i++){
                int p = t + i*256;
                ar[i] = *(const float4*)(Ab2 + (size_t)(p>>3)*CC + (p&7)*4);
                br[i] = *(const float4*)(Bb2 + (size_t)(p>>5)*CC + (p&31)*4);
            }
        }
#pragma unroll
        for (int s8=0; s8<4; s8++){
            uint32_t a[2][4];
            ldsm4(a[0], a_addr[0] + s8*32);
            ldsm4(a[1], a_addr[1] + s8*32);
            const float* bp = &Bs[(s8*8 + (lane&3))*BSN + wn*64 + (lane>>2)];
#pragma unroll
            for (int nf=0; nf<8; nf++){
                uint32_t b0 = __float_as_uint(bp[nf*8]);
                uint32_t b1 = __float_as_uint(bp[nf*8 + 4*BSN]);
                mma_tf32(acc[0][nf], a[0], b0, b1);
                mma_tf32(acc[1][nf], a[1], b0, b1);
            }
        }
    }

    // epilogue
#pragma unroll
    for (int mf=0; mf<2; mf++){
#pragma unroll
        for (int nf=0; nf<8; nf++){
            int r = bm*128 + wm*32 + mf*16 + (lane>>2);
            int c = bn*128 + wn*64 + nf*8 + (lane&3)*2;
#pragma unroll
            for (int half=0; half<2; half++){
                int rr = r + half*8;
                float2 v = make_float2(acc[mf][nf][half*2], acc[mf][nf][half*2+1]);
                if (SPLIT){
                    int b = rr >> 12, l = rr & 4095;
                    int n = l >> 4, s = l & 15;
                    int h = c >> 6, f = c & 63;
                    size_t idx = ((((size_t)(b*NHH + h)*NCC + n)*CSS + s)*HFF + f);
                    *(float2*)(out + idx) = v;
                } else {
                    *(float2*)(out + (size_t)rr*CC + c) = v;
                }
            }
        }
    }
}

// ---------------- ilr / coeff -----------------
__global__ void __launch_bounds__(256) ilr_kernel(const float* __restrict__ hs,
                                                  const float* __restrict__ ilw,
                                                  const float* __restrict__ ilb)
{
    const int h = threadIdx.x, rloc = threadIdx.y;
    const int row = blockIdx.x*16 + rloc;
    const float* hp = hs + (size_t)row*CC;
    float a0=0.f,a1=0.f,a2=0.f,a3=0.f;
    for (int k=0;k<CC;k+=4){
        float4 x = *(const float4*)(hp + k);
        a0 += x.x*ilw[(k+0)*NHH+h];
        a1 += x.y*ilw[(k+1)*NHH+h];
        a2 += x.z*ilw[(k+2)*NHH+h];
        a3 += x.w*ilw[(k+3)*NHH+h];
    }
    float acc = (a0+a1)+(a2+a3) + ilb[h];
    float sig = 1.f/(1.f+expf(-acc));
    int b = row>>12, l = row&4095, n = l>>4, s = l&15;
    g_coef[((size_t)(b*NHH+h)*NCC+n)*CSS+s] = sig*(1.f/(float)(s+1))*(1.f/(float)HFF);
}

// ---------------- TTT scan: one CTA per (b,h) chain (R1 known-good) ----------
#define O_W1   0            // 64 x 256
#define O_W2   16384        // 256 x 65
#define O_XA   33024        // 16 x 68
#define O_XB   34112
#define O_XC   35200
#define O_XBT  36288        // 64 x 20
#define O_Z1   37568        // 16 x 260
#define O_Z1T  41728        // 256 x 20
#define O_G1   46848        // 16 x 260
#define O_Z1B  51008        // 16 x 260
#define O_G2   55168        // 16 x 68
#define O_A1   56256        // 16 x 17
#define O_A2   56528        // 16 x 17
#define O_CO   56800        // 16
#define SCAN_SMEM_FLOATS 56816
#define SCAN_SMEM_BYTES  (SCAN_SMEM_FLOATS*4)

__global__ void __launch_bounds__(256, 1) scan_kernel(const float* __restrict__ W1g,
                                                      const float* __restrict__ W2g)
{
    extern __shared__ float sm[];
    float* sW1  = sm + O_W1;
    float* sW2  = sm + O_W2;
    float* sXA  = sm + O_XA;
    float* sXB  = sm + O_XB;
    float* sXC  = sm + O_XC;
    float* sXBt = sm + O_XBT;
    float* sZ1  = sm + O_Z1;
    float* sZ1t = sm + O_Z1T;
    float* sG1  = sm + O_G1;
    float* sZ1b = sm + O_Z1B;
    float* sG2  = sm + O_G2;
    float* sA1  = sm + O_A1;
    float* sA2  = sm + O_A2;
    float* sCo  = sm + O_CO;

    const int t  = threadIdx.x;
    const int bh = blockIdx.x;
    const int b  = bh >> 4, h = bh & 15;

    const float* w1p = W1g + (size_t)h*HFF*HF4;
    for (int i = t; i < HFF*HF4; i += 256) sW1[i] = w1p[i];
    const float* w2p = W2g + (size_t)h*HF4*HFF;
    for (int i = t; i < HF4*HFF; i += 256) sW2[(i>>6)*65 + (i&63)] = w2p[i];

    const size_t cbase = (size_t)bh * (NCC*CSS*HFF);

    for (int n = 0; n < NCC; n++) {
        {
            const float4* xa4 = (const float4*)(g_XA + cbase + (size_t)n*1024);
            const float4* xb4 = (const float4*)(g_XB + cbase + (size_t)n*1024);
            const float4* xc4 = (const float4*)(g_XC + cbase + (size_t)n*1024);
            int e = t*4, s = e >> 6, f = e & 63;
            float4 va = xa4[t], vb = xb4[t], vc = xc4[t];
            *(float4*)(sXA + s*68 + f) = va;
            *(float4*)(sXB + s*68 + f) = vb;
            *(float4*)(sXC + s*68 + f) = vc;
            sXBt[(f+0)*20 + s] = vb.x;
            sXBt[(f+1)*20 + s] = vb.y;
            sXBt[(f+2)*20 + s] = vb.z;
            sXBt[(f+3)*20 + s] = vb.w;
            if (t < 16) sCo[t] = g_coef[(size_t)bh*(NCC*CSS) + n*CSS + t];
        }
        __syncthreads();

        // Step 1: Z1 = XB@W1, P = XC@W1
        {
            const int j = t;
            float acc1[16], accP[16];
#pragma unroll
            for (int s=0;s<16;s++){acc1[s]=0.f;accP[s]=0.f;}
#pragma unroll
            for (int kb=0; kb<64; kb+=16) {
                float w[16];
#pragma unroll
                for (int kk=0;kk<16;kk++) w[kk] = sW1[(kb+kk)*256 + j];
#pragma unroll
                for (int s=0;s<16;s++) {
                    const float4* xb = (const float4*)(sXB + s*68 + kb);
                    const float4* xc = (const float4*)(sXC + s*68 + kb);
#pragma unroll
                    for (int q=0;q<4;q++) {
                        float4 vb = xb[q], vc = xc[q];
                        acc1[s] += vb.x*w[4*q] + vb.y*w[4*q+1] + vb.z*w[4*q+2] + vb.w*w[4*q+3];
                        accP[s] += vc.x*w[4*q] + vc.y*w[4*q+1] + vc.z*w[4*q+2] + vc.w*w[4*q+3];
                    }
                }
            }
#pragma unroll
            for (int s=0;s<16;s++) {
                sZ1 [s*260 + j] = acc1[s];
                sZ1t[j*20 + s]  = acc1[s];
                sZ1b[s*260 + j] = accP[s];
            }
        }
        __syncthreads();

        // Step 2: Z2 = Z1@W2 ; g2 = Z2 - XA
        {
            const int f = t & 63, si = t >> 6;
            float acc[4] = {0.f,0.f,0.f,0.f};
#pragma unroll 4
            for (int kb=0; kb<256; kb+=4) {
                float w0 = sW2[(kb+0)*65 + f];
                float w1 = sW2[(kb+1)*65 + f];
                float w2 = sW2[(kb+2)*65 + f];
                float w3 = sW2[(kb+3)*65 + f];
#pragma unroll
                for (int q=0;q<4;q++) {
                    const float4 z = *(const float4*)(sZ1 + (si*4+q)*260 + kb);
                    acc[q] += z.x*w0 + z.y*w1 + z.z*w2 + z.w*w3;
                }
            }
#pragma unroll
            for (int q=0;q<4;q++) {
                int s = si*4+q;
                sG2[s*68 + f] = acc[q] - sXA[s*68 + f];
            }
        }
        // A1 = tril(XC @ XB^T)
        {
            const int si = t >> 4, sj = t & 15;
            float acc = 0.f;
            if (sj <= si) {
#pragma unroll
                for (int k=0;k<64;k+=4) {
                    float4 xc = *(const float4*)(sXC + si*68 + k);
                    float4 xb = *(const float4*)(sXB + sj*68 + k);
                    acc += xc.x*xb.x + xc.y*xb.y + xc.z*xb.z + xc.w*xb.w;
                }
            }
            sA1[si*17 + sj] = acc;
        }
        __syncthreads();

        // Step 3: g1 = g2 @ W2^T
        {
            const int j = t;
            float acc[16];
#pragma unroll
            for (int s=0;s<16;s++) acc[s]=0.f;
#pragma unroll
            for (int fb=0; fb<64; fb+=16) {
                float w[16];
#pragma unroll
                for (int kk=0;kk<16;kk++) w[kk] = sW2[j*65 + fb + kk];
#pragma unroll
                for (int s=0;s<16;s++) {
                    const float4* g4 = (const float4*)(sG2 + s*68 + fb);
#pragma unroll
                    for (int q=0;q<4;q++) {
                        float4 g = g4[q];
                        acc[s] += g.x*w[4*q] + g.y*w[4*q+1] + g.z*w[4*q+2] + g.w*w[4*q+3];
                    }
                }
            }
#pragma unroll
            for (int s=0;s<16;s++) sG1[s*260 + j] = acc[s];
        }
        __syncthreads();

        // Step 5: Z1_bar = P - coeff*(A1@g1) ; Step 6: W1 -= cl*(XB^T@g1)
        {
            const int j = t;
            float g1c[16];
#pragma unroll
            for (int u=0;u<16;u++) g1c[u] = sG1[u*260 + j];
#pragma unroll
            for (int s=0;s<16;s++) {
                float a = 0.f;
                for (int u=0;u<=s;u++) a += sA1[s*17+u]*g1c[u];
                sZ1b[s*260 + j] -= sCo[s]*a;
            }
            const float cl = sCo[15];
#pragma unroll 4
            for (int k=0;k<64;k++) {
                float a = 0.f;
#pragma unroll
                for (int q=0;q<4;q++) {
                    float4 xb = *(const float4*)(sXBt + k*20 + 4*q);
                    a += xb.x*g1c[4*q] + xb.y*g1c[4*q+1] + xb.z*g1c[4*q+2] + xb.w*g1c[4*q+3];
                }
                sW1[k*256 + j] -= cl*a;
            }
        }
        __syncthreads();

        // Step 7: A2 = tril(Z1_bar @ Z1^T)
        {
            const int si = t >> 4, sj = t & 15;
            float acc = 0.f;
            if (sj <= si) {
#pragma unroll 8
                for (int k=0;k<256;k+=4) {
                    float4 zb = *(const float4*)(sZ1b + si*260 + k);
                    float4 zz = *(const float4*)(sZ1  + sj*260 + k);
                    acc += zb.x*zz.x + zb.y*zz.y + zb.z*zz.z + zb.w*zz.w;
                }
            }
            sA2[si*17 + sj] = acc;
        }
        __syncthreads();

        // Step 8: Z2_bar = Z1_bar@W2 - coeff*(A2@g2)
        {
            const int f = t & 63, si = t >> 6;
            float acc[4] = {0.f,0.f,0.f,0.f};
#pragma unroll 4
            for (int kb=0; kb<256; kb+=4) {
                float w0 = sW2[(kb+0)*65 + f];
                float w1 = sW2[(kb+1)*65 + f];
                float w2 = sW2[(kb+2)*65 + f];
                float w3 = sW2[(kb+3)*65 + f];
#pragma unroll
                for (int q=0;q<4;q++) {
                    const float4 z = *(const float4*)(sZ1b + (si*4+q)*260 + kb);
                    acc[q] += z.x*w0 + z.y*w1 + z.z*w2 + z.w*w3;
                }
            }
            float* orow = g_Z2b + (size_t)(b*LL + n*CSS)*CC + h*HFF + f;
#pragma unroll
            for (int q=0;q<4;q++) {
                int s = si*4+q;
                float c = 0.f;
                for (int u=0;u<=s;u++) c += sA2[s*17+u]*sG2[u*68+f];
                orow[(size_t)s*CC] = acc[q] - sCo[s]*c;
            }
        }
        __syncthreads();

        // Step 9: W2 -= cl*(Z1^T @ g2)
        {
            const int f = t & 63, ko = t >> 6;
            float g2c[16];
#pragma unroll
            for (int s=0;s<16;s++) g2c[s] = sG2[s*68 + f];
            const float cl = sCo[15];
#pragma unroll 2
            for (int i=0;i<64;i++) {
                int k = ko*64 + i;
                float a = 0.f;
#pragma unroll
                for (int q=0;q<4;q++) {
                    float4 z = *(const float4*)(sZ1t + k*20 + 4*q);
                    a += z.x*g2c[4*q] + z.y*g2c[4*q+1] + z.z*g2c[4*q+2] + z.w*g2c[4*q+3];
                }
                sW2[k*65 + f] -= cl*a;
            }
        }
        __syncthreads();
    }
}

// ---------------- launch -----------------
extern "C" void kernel_launch(void* const* d_in, const int* in_sizes, int n_in,
                              void* d_out, int out_size)
{
    const float* hs  = (const float*)d_in[0];
    const float* Wq  = (const float*)d_in[1];
    const float* Wk  = (const float*)d_in[2];
    const float* Wv  = (const float*)d_in[3];
    const float* Wo  = (const float*)d_in[4];
    const float* ilw = (const float*)d_in[5];
    const float* ilb = (const float*)d_in[6];
    const float* W1  = (const float*)d_in[7];
    const float* W2  = (const float*)d_in[8];
    float* out = (float*)d_out;

    cudaFuncSetAttribute(scan_kernel, cudaFuncAttributeMaxDynamicSharedMemorySize,
                         SCAN_SMEM_BYTES);

    void *pXA, *pXB, *pXC, *pZ2b;
    cudaGetSymbolAddress(&pXA, g_XA);
    cudaGetSymbolAddress(&pXB, g_XB);
    cudaGetSymbolAddress(&pXC, g_XC);
    cudaGetSymbolAddress(&pZ2b, g_Z2b);

    dim3 gg(CC/128, MROWS/128);   // (8, 128)
    gemm_tf32<1><<<gg, 256>>>(hs, Wq, (float*)pXC);
    gemm_tf32<1><<<gg, 256>>>(hs, Wk, (float*)pXB);
    gemm_tf32<1><<<gg, 256>>>(hs, Wv, (float*)pXA);
    ilr_kernel<<<MROWS/16, dim3(16,16)>>>(hs, ilw, ilb);
    scan_kernel<<<BB*NHH, 256, SCAN_SMEM_BYTES>>>(W1, W2);
    gemm_tf32<0><<<gg, 256>>>((const float*)pZ2b, Wo, out);
}

// round 4
// speedup vs baseline: 1.7663x; 1.4603x over previous
#include <cuda_runtime.h>
#include <math.h>
#include <stdint.h>

#define BB 4
#define LL 4096
#define CC 1024
#define NHH 16
#define CSS 16
#define HFF 64
#define HF4 256
#define NCC 256
#define MROWS (BB*LL)   // 16384

// ---------------- device scratch -----------------
__device__ float g_XA[BB*NHH*NCC*CSS*HFF];
__device__ float g_XB[BB*NHH*NCC*CSS*HFF];
__device__ float g_XC[BB*NHH*NCC*CSS*HFF];
__device__ float g_coef[BB*NHH*NCC*CSS];
__device__ float g_Z2b[(size_t)MROWS*CC];

// ---------------- helpers -----------------
__device__ __forceinline__ float to_tf32(float x){
    uint32_t u; asm("cvt.rna.tf32.f32 %0, %1;" : "=r"(u) : "f"(x));
    return __uint_as_float(u);
}
__device__ __forceinline__ uint32_t f2tf(float x){
    uint32_t u; asm("cvt.rna.tf32.f32 %0, %1;" : "=r"(u) : "f"(x));
    return u;
}
__device__ __forceinline__ void splitf(float v, uint32_t& h, uint32_t& l){
    h = f2tf(v);
    l = f2tf(v - __uint_as_float(h));
}
__device__ __forceinline__ void ldsm4(uint32_t* r, uint32_t addr){
    asm volatile("ldmatrix.sync.aligned.m8n8.x4.shared.b16 {%0,%1,%2,%3}, [%4];"
        : "=r"(r[0]),"=r"(r[1]),"=r"(r[2]),"=r"(r[3]) : "r"(addr));
}
__device__ __forceinline__ void mma_tf32(float* c, const uint32_t* a, uint32_t b0, uint32_t b1){
    asm volatile("mma.sync.aligned.m16n8k8.row.col.f32.tf32.tf32.f32 "
        "{%0,%1,%2,%3},{%4,%5,%6,%7},{%8,%9},{%0,%1,%2,%3};"
        : "+f"(c[0]),"+f"(c[1]),"+f"(c[2]),"+f"(c[3])
        : "r"(a[0]),"r"(a[1]),"r"(a[2]),"r"(a[3]),"r"(b0),"r"(b1));
}
__device__ __forceinline__ void mma3(float* c, const uint32_t* ah, const uint32_t* al,
                                     const uint32_t* bh, const uint32_t* bl){
    mma_tf32(c, ah, bh[0], bh[1]);
    mma_tf32(c, ah, bl[0], bl[1]);
    mma_tf32(c, al, bh[0], bh[1]);
}
// A frag (rows r=0..15 implied; cols k0..k0+7) from S[row][col], row-stride ld
__device__ __forceinline__ void ldAf(const float* S, int ld, int k0, int lane,
                                     uint32_t* ah, uint32_t* al, float scale){
    int g = lane >> 2, tg = lane & 3;
    float v0 = S[g*ld + k0+tg]       * scale;
    float v1 = S[(g+8)*ld + k0+tg]   * scale;
    float v2 = S[g*ld + k0+tg+4]     * scale;
    float v3 = S[(g+8)*ld + k0+tg+4] * scale;
    splitf(v0, ah[0], al[0]); splitf(v1, ah[1], al[1]);
    splitf(v2, ah[2], al[2]); splitf(v3, ah[3], al[3]);
}
// A frag from transposed source: A[m][k] = S[k][m], m-rows m0..m0+15
__device__ __forceinline__ void ldAfT(const float* S, int ld, int m0, int k0, int lane,
                                      uint32_t* ah, uint32_t* al, float scale){
    int g = lane >> 2, tg = lane & 3;
    float v0 = S[(k0+tg)*ld + m0+g]     * scale;
    float v1 = S[(k0+tg)*ld + m0+g+8]   * scale;
    float v2 = S[(k0+tg+4)*ld + m0+g]   * scale;
    float v3 = S[(k0+tg+4)*ld + m0+g+8] * scale;
    splitf(v0, ah[0], al[0]); splitf(v1, ah[1], al[1]);
    splitf(v2, ah[2], al[2]); splitf(v3, ah[3], al[3]);
}
// B frag: B[k][n] from S rows=k
__device__ __forceinline__ void ldBf(const float* S, int ld, int k0, int n0, int lane,
                                     uint32_t* bh, uint32_t* bl){
    int g = lane >> 2, tg = lane & 3;
    splitf(S[(k0+tg)*ld + n0+g],   bh[0], bl[0]);
    splitf(S[(k0+tg+4)*ld + n0+g], bh[1], bl[1]);
}
// B frag transposed: B[k][n] = S[n][k]
__device__ __forceinline__ void ldBfT(const float* S, int ld, int k0, int n0, int lane,
                                      uint32_t* bh, uint32_t* bl){
    int g = lane >> 2, tg = lane & 3;
    splitf(S[(n0+g)*ld + k0+tg],   bh[0], bl[0]);
    splitf(S[(n0+g)*ld + k0+tg+4], bh[1], bl[1]);
}

// ---------------- tf32 tensor-core GEMM (unchanged from R3) ------------------
#define GPAD 36
#define BSN  132
template<int SPLIT>
__global__ void __launch_bounds__(256) gemm_tf32(const float* __restrict__ A,
                                                 const float* __restrict__ Wm,
                                                 float* __restrict__ out)
{
    __shared__ float As[128*GPAD];
    __shared__ float Bs[32*BSN];
    const int t = threadIdx.x, lane = t & 31, warp = t >> 5;
    const int wm = warp >> 1, wn = warp & 1;
    const int bm = blockIdx.y, bn = blockIdx.x;

    float acc[2][8][4];
#pragma unroll
    for (int i=0;i<2;i++)
#pragma unroll
        for (int j=0;j<8;j++)
#pragma unroll
            for (int q=0;q<4;q++) acc[i][j][q]=0.f;

    uint32_t As_u = (uint32_t)__cvta_generic_to_shared(As);
    uint32_t a_addr[2];
#pragma unroll
    for (int mf=0; mf<2; mf++) {
        int row = wm*32 + mf*16 + (lane & 15);
        a_addr[mf] = As_u + (uint32_t)(row*GPAD + (lane>>4)*4) * 4u;
    }

    const float* Ab = A  + (size_t)(bm*128)*CC;
    const float* Bb = Wm + bn*128;

    float4 ar[4], br[4];
#pragma unroll
    for (int i=0;i<4;i++){
        int p = t + i*256;
        ar[i] = *(const float4*)(Ab + (size_t)(p>>3)*CC + (p&7)*4);
        br[i] = *(const float4*)(Bb + (size_t)(p>>5)*CC + (p&31)*4);
    }

    for (int it=0; it<32; it++){
        __syncthreads();
#pragma unroll
        for (int i=0;i<4;i++){
            int p = t + i*256;
            float4 v = ar[i];
            float4 w = make_float4(to_tf32(v.x), to_tf32(v.y), to_tf32(v.z), to_tf32(v.w));
            *(float4*)&As[(p>>3)*GPAD + (p&7)*4] = w;
        }
#pragma unroll
        for (int i=0;i<4;i++){
            int p = t + i*256;
            float4 v = br[i];
            float4 w = make_float4(to_tf32(v.x), to_tf32(v.y), to_tf32(v.z), to_tf32(v.w));
            *(float4*)&Bs[(p>>5)*BSN + (p&31)*4] = w;
        }
        __syncthreads();
        if (it < 31){
            const float* Ab2 = Ab + (it+1)*32;
            const float* Bb2 = Bb + (size_t)(it+1)*32*CC;
#pragma unroll
            for (int i=0;i<4;i++){
                int p = t + i*256;
                ar[i] = *(const float4*)(Ab2 + (size_t)(p>>3)*CC + (p&7)*4);
                br[i] = *(const float4*)(Bb2 + (size_t)(p>>5)*CC + (p&31)*4);
            }
        }
#pragma unroll
        for (int s8=0; s8<4; s8++){
            uint32_t a[2][4];
            ldsm4(a[0], a_addr[0] + s8*32);
            ldsm4(a[1], a_addr[1] + s8*32);
            const float* bp = &Bs[(s8*8 + (lane&3))*BSN + wn*64 + (lane>>2)];
#pragma unroll
            for (int nf=0; nf<8; nf++){
                uint32_t b0 = __float_as_uint(bp[nf*8]);
                uint32_t b1 = __float_as_uint(bp[nf*8 + 4*BSN]);
                mma_tf32(acc[0][nf], a[0], b0, b1);
                mma_tf32(acc[1][nf], a[1], b0, b1);
            }
        }
    }
#pragma unroll
    for (int mf=0; mf<2; mf++){
#pragma unroll
        for (int nf=0; nf<8; nf++){
            int r = bm*128 + wm*32 + mf*16 + (lane>>2);
            int c = bn*128 + wn*64 + nf*8 + (lane&3)*2;
#pragma unroll
            for (int half=0; half<2; half++){
                int rr = r + half*8;
                float2 v = make_float2(acc[mf][nf][half*2], acc[mf][nf][half*2+1]);
                if (SPLIT){
                    int b = rr >> 12, l = rr & 4095;
                    int n = l >> 4, s = l & 15;
                    int h = c >> 6, f = c & 63;
                    size_t idx = ((((size_t)(b*NHH + h)*NCC + n)*CSS + s)*HFF + f);
                    *(float2*)(out + idx) = v;
                } else {
                    *(float2*)(out + (size_t)rr*CC + c) = v;
                }
            }
        }
    }
}

// ---------------- ilr / coeff -----------------
__global__ void __launch_bounds__(256) ilr_kernel(const float* __restrict__ hs,
                                                  const float* __restrict__ ilw,
                                                  const float* __restrict__ ilb)
{
    const int h = threadIdx.x, rloc = threadIdx.y;
    const int row = blockIdx.x*16 + rloc;
    const float* hp = hs + (size_t)row*CC;
    float a0=0.f,a1=0.f,a2=0.f,a3=0.f;
    for (int k=0;k<CC;k+=4){
        float4 x = *(const float4*)(hp + k);
        a0 += x.x*ilw[(k+0)*NHH+h];
        a1 += x.y*ilw[(k+1)*NHH+h];
        a2 += x.z*ilw[(k+2)*NHH+h];
        a3 += x.w*ilw[(k+3)*NHH+h];
    }
    float acc = (a0+a1)+(a2+a3) + ilb[h];
    float sig = 1.f/(1.f+expf(-acc));
    int b = row>>12, l = row&4095, n = l>>4, s = l&15;
    g_coef[((size_t)(b*NHH+h)*NCC+n)*CSS+s] = sig*(1.f/(float)(s+1))*(1.f/(float)HFF);
}

// ---------------- TTT scan: split-tf32 tensor-core version -------------------
// smem float offsets
#define S_W1   0                        // 64 x 264
#define S_W2   (S_W1 + 64*264)          // 256 x 72
#define S_XA   (S_W2 + 256*72)          // 16 x 68
#define S_XB   (S_XA + 16*68)
#define S_XC   (S_XB + 16*68)
#define S_Z1   (S_XC + 16*68)           // 16 x 264
#define S_Z1B  (S_Z1 + 16*264)          // 16 x 264
#define S_G1   (S_Z1B + 16*264)         // 16 x 264
#define S_G2   (S_G1 + 16*264)          // 16 x 72
#define S_A1M  (S_G2 + 16*72)           // 16 x 20  (pre-negated, coeff-scaled, tril)
#define S_A2M  (S_A1M + 16*20)          // 16 x 20
#define S_ST   (S_A2M + 16*20)          // 8 x 16 x 18 staging for A2 partials
#define S_CO   (S_ST + 8*16*18)         // 16
#define SCAN_SMEM_FLOATS (S_CO + 16)
#define SCAN_SMEM_BYTES  (SCAN_SMEM_FLOATS*4)

__global__ void __launch_bounds__(256, 1) scan_kernel(const float* __restrict__ W1g,
                                                      const float* __restrict__ W2g)
{
    extern __shared__ float sm[];
    float* sW1  = sm + S_W1;
    float* sW2  = sm + S_W2;
    float* sXA  = sm + S_XA;
    float* sXB  = sm + S_XB;
    float* sXC  = sm + S_XC;
    float* sZ1  = sm + S_Z1;
    float* sZ1b = sm + S_Z1B;
    float* sG1  = sm + S_G1;
    float* sG2  = sm + S_G2;
    float* sA1m = sm + S_A1M;
    float* sA2m = sm + S_A2M;
    float* sSt  = sm + S_ST;
    float* sCo  = sm + S_CO;

    const int t = threadIdx.x;
    const int lane = t & 31, w = t >> 5;
    const int g = lane >> 2, tg = lane & 3;
    const int bh = blockIdx.x;
    const int b  = bh >> 4, h = bh & 15;

    // initial state load
    const float* w1p = W1g + (size_t)h*HFF*HF4;
    for (int i = t; i < HFF*HF4; i += 256) sW1[(i>>8)*264 + (i&255)] = w1p[i];
    const float* w2p = W2g + (size_t)h*HF4*HFF;
    for (int i = t; i < HF4*HFF; i += 256) sW2[(i>>6)*72 + (i&63)] = w2p[i];

    const size_t cbase = (size_t)bh * (NCC*CSS*HFF);

    for (int n = 0; n < NCC; n++) {
        // ---- chunk load ----
        {
            const float4* xa4 = (const float4*)(g_XA + cbase + (size_t)n*1024);
            const float4* xb4 = (const float4*)(g_XB + cbase + (size_t)n*1024);
            const float4* xc4 = (const float4*)(g_XC + cbase + (size_t)n*1024);
            int e = t*4, s = e >> 6, f = e & 63;
            *(float4*)(sXA + s*68 + f) = xa4[t];
            *(float4*)(sXB + s*68 + f) = xb4[t];
            *(float4*)(sXC + s*68 + f) = xc4[t];
            if (t < 16) sCo[t] = g_coef[(size_t)bh*(NCC*CSS) + n*CSS + t];
        }
        __syncthreads();

        // ---- P1: Z1 = XB@W1 ; P(->Z1b) = XC@W1.  warp w: n0 = w*32 ----
        {
            const int n0 = w*32;
            float aZ[4][4], aP[4][4];
#pragma unroll
            for (int i=0;i<4;i++)
#pragma unroll
                for (int q=0;q<4;q++){ aZ[i][q]=0.f; aP[i][q]=0.f; }
#pragma unroll
            for (int ks=0; ks<8; ks++){
                int k0 = ks*8;
                uint32_t aBh[4],aBl[4],aCh[4],aCl[4];
                ldAf(sXB, 68, k0, lane, aBh, aBl, 1.f);
                ldAf(sXC, 68, k0, lane, aCh, aCl, 1.f);
#pragma unroll
                for (int nf=0; nf<4; nf++){
                    uint32_t bhf[2], blf[2];
                    ldBf(sW1, 264, k0, n0+nf*8, lane, bhf, blf);
                    mma3(aZ[nf], aBh, aBl, bhf, blf);
                    mma3(aP[nf], aCh, aCl, bhf, blf);
                }
            }
#pragma unroll
            for (int nf=0; nf<4; nf++){
                int col = n0 + nf*8 + 2*tg;
                *(float2*)&sZ1 [g*264 + col]     = make_float2(aZ[nf][0], aZ[nf][1]);
                *(float2*)&sZ1 [(g+8)*264 + col] = make_float2(aZ[nf][2], aZ[nf][3]);
                *(float2*)&sZ1b[g*264 + col]     = make_float2(aP[nf][0], aP[nf][1]);
                *(float2*)&sZ1b[(g+8)*264 + col] = make_float2(aP[nf][2], aP[nf][3]);
            }
        }
        __syncthreads();

        // ---- P2: Z2 = Z1@W2 ; g2 = Z2 - XA.  warp w: n0 = w*8.
        //      warps 0,1 additionally: A1m = -co*tril(XC@XB^T) ----
        {
            const int n0 = w*8;
            float acc[4] = {0.f,0.f,0.f,0.f};
#pragma unroll 4
            for (int ks=0; ks<32; ks++){
                int k0 = ks*8;
                uint32_t ah[4],al[4],bhf[2],blf[2];
                ldAf(sZ1, 264, k0, lane, ah, al, 1.f);
                ldBf(sW2, 72, k0, n0, lane, bhf, blf);
                mma3(acc, ah, al, bhf, blf);
            }
            {
                int col = n0 + 2*tg;
                float2 x0 = *(float2*)&sXA[g*68 + col];
                float2 x1 = *(float2*)&sXA[(g+8)*68 + col];
                *(float2*)&sG2[g*72 + col]     = make_float2(acc[0]-x0.x, acc[1]-x0.y);
                *(float2*)&sG2[(g+8)*72 + col] = make_float2(acc[2]-x1.x, acc[3]-x1.y);
            }
            if (w < 2){
                const int an0 = w*8;
                float a1[4] = {0.f,0.f,0.f,0.f};
#pragma unroll
                for (int ks=0; ks<8; ks++){
                    int k0 = ks*8;
                    uint32_t ah[4],al[4],bhf[2],blf[2];
                    ldAf(sXC, 68, k0, lane, ah, al, 1.f);
                    ldBfT(sXB, 68, k0, an0, lane, bhf, blf);
                    mma3(a1, ah, al, bhf, blf);
                }
                int u0 = an0 + 2*tg;
                int s0 = g, s1 = g+8;
                sA1m[s0*20 + u0]   = (u0   <= s0) ? -sCo[s0]*a1[0] : 0.f;
                sA1m[s0*20 + u0+1] = (u0+1 <= s0) ? -sCo[s0]*a1[1] : 0.f;
                sA1m[s1*20 + u0]   = (u0   <= s1) ? -sCo[s1]*a1[2] : 0.f;
                sA1m[s1*20 + u0+1] = (u0+1 <= s1) ? -sCo[s1]*a1[3] : 0.f;
            }
        }
        __syncthreads();

        // ---- P3: g1 = g2 @ W2^T.  warp w: n0 = w*32 ----
        {
            const int n0 = w*32;
            float accG[4][4];
#pragma unroll
            for (int i=0;i<4;i++)
#pragma unroll
                for (int q=0;q<4;q++) accG[i][q]=0.f;
#pragma unroll
            for (int ks=0; ks<8; ks++){
                int k0 = ks*8;
                uint32_t ah[4],al[4];
                ldAf(sG2, 72, k0, lane, ah, al, 1.f);
#pragma unroll
                for (int nf=0; nf<4; nf++){
                    uint32_t bhf[2], blf[2];
                    ldBfT(sW2, 72, k0, n0+nf*8, lane, bhf, blf);
                    mma3(accG[nf], ah, al, bhf, blf);
                }
            }
#pragma unroll
            for (int nf=0; nf<4; nf++){
                int col = n0 + nf*8 + 2*tg;
                *(float2*)&sG1[g*264 + col]     = make_float2(accG[nf][0], accG[nf][1]);
                *(float2*)&sG1[(g+8)*264 + col] = make_float2(accG[nf][2], accG[nf][3]);
            }
        }
        __syncthreads();

        // ---- P4: Z1b += A1m@g1 (corr1) ; W1 += (-cl*XB)^T @ g1 ----
        {
            const int n0 = w*32;
            float c1[4][4];
#pragma unroll
            for (int i=0;i<4;i++)
#pragma unroll
                for (int q=0;q<4;q++) c1[i][q]=0.f;
#pragma unroll
            for (int ks=0; ks<2; ks++){
                int k0 = ks*8;
                uint32_t ah[4],al[4];
                ldAf(sA1m, 20, k0, lane, ah, al, 1.f);
#pragma unroll
                for (int nf=0; nf<4; nf++){
                    uint32_t bhf[2], blf[2];
                    ldBf(sG1, 264, k0, n0+nf*8, lane, bhf, blf);
                    mma3(c1[nf], ah, al, bhf, blf);
                }
            }
#pragma unroll
            for (int nf=0; nf<4; nf++){
                int col = n0 + nf*8 + 2*tg;
                float2 v0 = *(float2*)&sZ1b[g*264 + col];
                float2 v1 = *(float2*)&sZ1b[(g+8)*264 + col];
                v0.x += c1[nf][0]; v0.y += c1[nf][1];
                v1.x += c1[nf][2]; v1.y += c1[nf][3];
                *(float2*)&sZ1b[g*264 + col]     = v0;
                *(float2*)&sZ1b[(g+8)*264 + col] = v1;
            }
            // W1 update: M=64, warp w -> m0=(w>>1)*16, nbase=(w&1)*128
            const float cl = sCo[15];
            const int m0 = (w>>1)*16, nbase = (w&1)*128;
#pragma unroll
            for (int half=0; half<2; half++){
                float wa[8][4];
#pragma unroll
                for (int i=0;i<8;i++)
#pragma unroll
                    for (int q=0;q<4;q++) wa[i][q]=0.f;
#pragma unroll
                for (int ks=0; ks<2; ks++){
                    int k0 = ks*8;
                    uint32_t ah[4],al[4];
                    ldAfT(sXB, 68, m0, k0, lane, ah, al, -cl);
#pragma unroll
                    for (int nf=0; nf<8; nf++){
                        uint32_t bhf[2], blf[2];
                        ldBf(sG1, 264, k0, nbase + half*64 + nf*8, lane, bhf, blf);
                        mma3(wa[nf], ah, al, bhf, blf);
                    }
                }
#pragma unroll
                for (int nf=0; nf<8; nf++){
                    int col = nbase + half*64 + nf*8 + 2*tg;
                    float2 v0 = *(float2*)&sW1[(m0+g)*264 + col];
                    float2 v1 = *(float2*)&sW1[(m0+g+8)*264 + col];
                    v0.x += wa[nf][0]; v0.y += wa[nf][1];
                    v1.x += wa[nf][2]; v1.y += wa[nf][3];
                    *(float2*)&sW1[(m0+g)*264 + col]   = v0;
                    *(float2*)&sW1[(m0+g+8)*264 + col] = v1;
                }
            }
        }
        __syncthreads();

        // ---- P5: Z2b main (regs) ; A2 partials (K-split, staged) ----
        float zacc[4] = {0.f,0.f,0.f,0.f};
        {
            const int n0 = w*8;
#pragma unroll 4
            for (int ks=0; ks<32; ks++){
                int k0 = ks*8;
                uint32_t ah[4],al[4],bhf[2],blf[2];
                ldAf(sZ1b, 264, k0, lane, ah, al, 1.f);
                ldBf(sW2, 72, k0, n0, lane, bhf, blf);
                mma3(zacc, ah, al, bhf, blf);
            }
            // A2 partial: K-slice kb = w*32
            float pa[2][4];
#pragma unroll
            for (int i=0;i<2;i++)
#pragma unroll
                for (int q=0;q<4;q++) pa[i][q]=0.f;
            const int kb = w*32;
#pragma unroll
            for (int ks=0; ks<4; ks++){
                int k0 = kb + ks*8;
                uint32_t ah[4],al[4];
                ldAf(sZ1b, 264, k0, lane, ah, al, 1.f);
#pragma unroll
                for (int nf=0; nf<2; nf++){
                    uint32_t bhf[2], blf[2];
                    ldBfT(sZ1, 264, k0, nf*8, lane, bhf, blf);
                    mma3(pa[nf], ah, al, bhf, blf);
                }
            }
#pragma unroll
            for (int nf=0; nf<2; nf++){
                int u = nf*8 + 2*tg;
                sSt[w*288 + g*18 + u]       = pa[nf][0];
                sSt[w*288 + g*18 + u+1]     = pa[nf][1];
                sSt[w*288 + (g+8)*18 + u]   = pa[nf][2];
                sSt[w*288 + (g+8)*18 + u+1] = pa[nf][3];
            }
        }
        __syncthreads();

        // ---- P5r: reduce A2 partials -> A2m = -co*tril(A2) ----
        {
            int s = t >> 4, u = t & 15;
            float sum = 0.f;
#pragma unroll
            for (int ww=0; ww<8; ww++) sum += sSt[ww*288 + s*18 + u];
            sA2m[s*20 + u] = (u <= s) ? -sCo[s]*sum : 0.f;
        }
        __syncthreads();

        // ---- P6: corr2 into zacc ; store out ; W2 update ----
        {
            const int n0 = w*8;
#pragma unroll
            for (int ks=0; ks<2; ks++){
                int k0 = ks*8;
                uint32_t ah[4],al[4],bhf[2],blf[2];
                ldAf(sA2m, 20, k0, lane, ah, al, 1.f);
                ldBf(sG2, 72, k0, n0, lane, bhf, blf);
                mma3(zacc, ah, al, bhf, blf);
            }
            {
                int col = h*HFF + n0 + 2*tg;
                size_t r0 = (size_t)(b*LL + n*CSS + g)*CC + col;
                size_t r1 = (size_t)(b*LL + n*CSS + g + 8)*CC + col;
                *(float2*)&g_Z2b[r0] = make_float2(zacc[0], zacc[1]);
                *(float2*)&g_Z2b[r1] = make_float2(zacc[2], zacc[3]);
            }
            // W2 update: M=256 -> warp w handles m0 in {w*32, w*32+16}
            const float cl = sCo[15];
#pragma unroll
            for (int mb=0; mb<2; mb++){
                const int m0 = w*32 + mb*16;
                float wa[8][4];
#pragma unroll
                for (int i=0;i<8;i++)
#pragma unroll
                    for (int q=0;q<4;q++) wa[i][q]=0.f;
#pragma unroll
                for (int ks=0; ks<2; ks++){
                    int k0 = ks*8;
                    uint32_t ah[4],al[4];
                    ldAfT(sZ1, 264, m0, k0, lane, ah, al, -cl);
#pragma unroll
                    for (int nf=0; nf<8; nf++){
                        uint32_t bhf[2], blf[2];
                        ldBf(sG2, 72, k0, nf*8, lane, bhf, blf);
                        mma3(wa[nf], ah, al, bhf, blf);
                    }
                }
#pragma unroll
                for (int nf=0; nf<8; nf++){
                    int col = nf*8 + 2*tg;
                    float2 v0 = *(float2*)&sW2[(m0+g)*72 + col];
                    float2 v1 = *(float2*)&sW2[(m0+g+8)*72 + col];
                    v0.x += wa[nf][0]; v0.y += wa[nf][1];
                    v1.x += wa[nf][2]; v1.y += wa[nf][3];
                    *(float2*)&sW2[(m0+g)*72 + col]   = v0;
                    *(float2*)&sW2[(m0+g+8)*72 + col] = v1;
                }
            }
        }
        __syncthreads();
    }
}

// ---------------- launch -----------------
extern "C" void kernel_launch(void* const* d_in, const int* in_sizes, int n_in,
                              void* d_out, int out_size)
{
    const float* hs  = (const float*)d_in[0];
    const float* Wq  = (const float*)d_in[1];
    const float* Wk  = (const float*)d_in[2];
    const float* Wv  = (const float*)d_in[3];
    const float* Wo  = (const float*)d_in[4];
    const float* ilw = (const float*)d_in[5];
    const float* ilb = (const float*)d_in[6];
    const float* W1  = (const float*)d_in[7];
    const float* W2  = (const float*)d_in[8];
    float* out = (float*)d_out;

    cudaFuncSetAttribute(scan_kernel, cudaFuncAttributeMaxDynamicSharedMemorySize,
                         SCAN_SMEM_BYTES);

    void *pXA, *pXB, *pXC, *pZ2b;
    cudaGetSymbolAddress(&pXA, g_XA);
    cudaGetSymbolAddress(&pXB, g_XB);
    cudaGetSymbolAddress(&pXC, g_XC);
    cudaGetSymbolAddress(&pZ2b, g_Z2b);

    dim3 gg(CC/128, MROWS/128);   // (8, 128)
    gemm_tf32<1><<<gg, 256>>>(hs, Wq, (float*)pXC);
    gemm_tf32<1><<<gg, 256>>>(hs, Wk, (float*)pXB);
    gemm_tf32<1><<<gg, 256>>>(hs, Wv, (float*)pXA);
    ilr_kernel<<<MROWS/16, dim3(16,16)>>>(hs, ilw, ilb);
    scan_kernel<<<BB*NHH, 256, SCAN_SMEM_BYTES>>>(W1, W2);
    gemm_tf32<0><<<gg, 256>>>((const float*)pZ2b, Wo, out);
}